// round 8
// baseline (speedup 1.0000x reference)
#include <cuda_runtime.h>
#include <cuda_fp16.h>
#include <cstdint>

#define Bn 8192
#define En 16
#define Zn 256
#define Hn 1024
#define Un 256
#define TMm 128                  // M tile
#define MAXT 80                  // max tiles
#define NT 256                   // threads per CTA (8 warps)
#define NTPRE 512
#define KC 64
#define BPART 32768              // B buffer: 256 rows x 128B (swizzled)

// smem byte offsets (all swizzled, no padding)
#define OAS 0                    // z/u tile: 128 x 512B = 64KB
#define OA2 65536                // a tile:   128 x 512B = 64KB
#define OBS 131072               // B ring: 3 x 32KB
#define SMEM_DYN (OBS + 3*BPART) // 229376

// ---------------- device scratch ----------------
__device__ int g_perm[Bn];
__device__ int g_te[MAXT], g_ts[MAXT], g_tr[MAXT];
__device__ int g_ntiles;
__device__ __half g_Wzh[(size_t)En*Zn*Zn];
__device__ __half g_Whh[(size_t)En*Hn*Zn];
__device__ __half g_Wuh[(size_t)En*Un*Un];

// ---------------- helpers ----------------
__device__ __forceinline__ uint32_t s2u(const void* p) {
    uint32_t a;
    asm("{ .reg .u64 t; cvta.to.shared.u64 t, %1; cvt.u32.u64 %0, t; }" : "=r"(a) : "l"(p));
    return a;
}
__device__ __forceinline__ void cpa16(uint32_t dst, const void* src) {
    asm volatile("cp.async.ca.shared.global [%0], [%1], 16;" :: "r"(dst), "l"(src));
}
__device__ __forceinline__ void cpa_commit() { asm volatile("cp.async.commit_group;" ::: "memory"); }
template<int N> __device__ __forceinline__ void cpa_wait() {
    asm volatile("cp.async.wait_group %0;" :: "n"(N) : "memory");
}
__device__ __forceinline__ void ldm4(uint32_t r[4], uint32_t addr) {
    asm volatile("ldmatrix.sync.aligned.m8n8.x4.shared.b16 {%0,%1,%2,%3}, [%4];"
                 : "=r"(r[0]), "=r"(r[1]), "=r"(r[2]), "=r"(r[3]) : "r"(addr));
}
__device__ __forceinline__ void mma16816(float c[4], const uint32_t a[4], uint32_t b0, uint32_t b1) {
    asm volatile("mma.sync.aligned.m16n8k16.row.col.f32.f16.f16.f32 "
                 "{%0,%1,%2,%3}, {%4,%5,%6,%7}, {%8,%9}, {%0,%1,%2,%3};"
                 : "+f"(c[0]), "+f"(c[1]), "+f"(c[2]), "+f"(c[3])
                 : "r"(a[0]), "r"(a[1]), "r"(a[2]), "r"(a[3]), "r"(b0), "r"(b1));
}
// swizzled offsets: A rows are 512B (32 16B-units), B rows are 128B (8 units)
__device__ __forceinline__ uint32_t swA(uint32_t r, uint32_t c16) {
    return (r << 9) + ((c16 >> 3) << 7) + (((c16 & 7) ^ (r & 7)) << 4);
}
__device__ __forceinline__ uint32_t swB(uint32_t r, uint32_t c16) {
    return (r << 7) + ((c16 ^ (r & 7)) << 4);
}

// ---------------- fused pre-pass: weight cvt + setup ----------------
#define NWz4 (En*Zn*Zn/4)
#define NWh4 (En*Hn*Zn/4)
#define NWu4 (En*Un*Un/4)
#define NW4  (NWz4+NWh4+NWu4)
#define PREBLK (NW4/NTPRE)       // 3072

__global__ __launch_bounds__(NTPRE) void k_pre(const int* __restrict__ rng,
                                               const float* __restrict__ Wz,
                                               const float* __restrict__ Wh,
                                               const float* __restrict__ Wu) {
    if (blockIdx.x == PREBLK) {
        __shared__ int sc[En], soff[En], scur[En];
        const int tid = threadIdx.x, lane = tid & 31;
        if (tid < En) { sc[tid] = 0; scur[tid] = 0; }
        __syncthreads();
        for (int i = tid; i < Bn; i += NTPRE) {
            int e = rng[i];
            unsigned m = __match_any_sync(0xffffffffu, e);
            if (lane == __ffs(m) - 1) atomicAdd(&sc[e], __popc(m));
        }
        __syncthreads();
        if (tid == 0) {
            int acc = 0, nt = 0;
            for (int e = 0; e < En; e++) {
                soff[e] = acc;
                int c = sc[e];
                for (int s = 0; s < c; s += TMm) {
                    g_te[nt] = e;
                    g_ts[nt] = acc + s;
                    g_tr[nt] = (c - s) < TMm ? (c - s) : TMm;
                    nt++;
                }
                acc += c;
            }
            g_ntiles = nt;
        }
        __syncthreads();
        for (int i = tid; i < Bn; i += NTPRE) {
            int e = rng[i];
            unsigned m = __match_any_sync(0xffffffffu, e);
            int leader = __ffs(m) - 1;
            int rank = __popc(m & ((1u << lane) - 1u));
            int base = 0;
            if (lane == leader) base = atomicAdd(&scur[e], __popc(m));
            base = __shfl_sync(0xffffffffu, base, leader);
            g_perm[soff[e] + base + rank] = i;
        }
        return;
    }
    int i = blockIdx.x * NTPRE + threadIdx.x;
    const float* src; __half* dh; int j = i;
    if (j < NWz4)                { src = Wz; dh = g_Wzh; }
    else if ((j -= NWz4) < NWh4) { src = Wh; dh = g_Whh; }
    else { j -= NWh4;              src = Wu; dh = g_Wuh; }
    float4 v = __ldg((const float4*)src + j);
    union { __half2 h[2]; uint2 q; } P;
    P.h[0] = __floats2half2_rn(v.x, v.y);
    P.h[1] = __floats2half2_rn(v.z, v.w);
    ((uint2*)dh)[j] = P.q;
}

// ---------------- A staging: 128 gathered fp32 rows -> fp16 swizzled smem ----------------
__device__ __forceinline__ void stage_a32(char* smc, int off, const float* __restrict__ g,
                                          const int* ss, int tid) {
#pragma unroll
    for (int i = tid; i < TMm * 32; i += NT) {
        int r = i >> 5, c16 = i & 31;
        int s = ss[r];
        uint4 q = make_uint4(0u, 0u, 0u, 0u);
        if (s >= 0) {
            const float4 v0 = __ldg((const float4*)(g + (size_t)s * 256 + c16 * 8));
            const float4 v1 = __ldg((const float4*)(g + (size_t)s * 256 + c16 * 8 + 4));
            union { __half2 h[4]; uint4 u; } P;
            P.h[0] = __floats2half2_rn(v0.x, v0.y);
            P.h[1] = __floats2half2_rn(v0.z, v0.w);
            P.h[2] = __floats2half2_rn(v1.x, v1.y);
            P.h[3] = __floats2half2_rn(v1.z, v1.w);
            q = P.u;
        }
        *(uint4*)(smc + off + swA(r, c16)) = q;
    }
}

// B chunk: NREG*32 rows x 64 halves (8 16B units/row), swizzled
template<int NREG>
__device__ __forceinline__ void stage_b(uint32_t bbase, const __half* __restrict__ gB,
                                        int kc, int tid) {
#pragma unroll
    for (int i = tid; i < NREG * 256; i += NT) {
        int r = i >> 3, c16 = i & 7;
        cpa16(bbase + swB(r, c16), gB + (size_t)r * 256 + kc * KC + c16 * 8);
    }
}

// ---------------- GEMM: one 128 x (NREG*32) output chunk ----------------
// 8 warps 2x4; warp tile 64 x (NREG*8). NREG=8 -> N=256, NREG=4 -> N=128.
// 3-buffer B ring rotating across calls via rot.
template<int NREG>
__device__ __forceinline__ void gemm_nc(uint32_t aB, uint32_t obs, int rot,
                                        const __half* __restrict__ gB,
                                        float c[4][8][4], int tid) {
    const int lane = tid & 31, warp = tid >> 5;
    const int wm = warp >> 2, wn = warp & 3;
    const int l15 = lane & 15, l16 = lane >> 4;

#pragma unroll
    for (int mt = 0; mt < 4; mt++)
#pragma unroll
        for (int nt = 0; nt < NREG; nt++)
#pragma unroll
            for (int j = 0; j < 4; j++) c[mt][nt][j] = 0.f;

    stage_b<NREG>(obs + (uint32_t)(rot % 3) * BPART, gB, 0, tid);
    cpa_commit();

#pragma unroll
    for (int kc = 0; kc < 4; kc++) {
        if (kc < 3) {
            stage_b<NREG>(obs + (uint32_t)((rot + kc + 1) % 3) * BPART, gB, kc + 1, tid);
            cpa_commit();
            cpa_wait<1>();
        } else {
            cpa_wait<0>();
        }
        __syncthreads();

        const uint32_t bH = obs + (uint32_t)((rot + kc) % 3) * BPART;
#pragma unroll
        for (int k16 = 0; k16 < 4; k16++) {
            const uint32_t ac16 = (uint32_t)(kc * 8 + k16 * 2 + l16);
            uint32_t ah[4][4];
#pragma unroll
            for (int mt = 0; mt < 4; mt++)
                ldm4(ah[mt], aB + swA((uint32_t)(wm * 64 + mt * 16 + l15), ac16));
            uint32_t bf[NREG / 2][4];
#pragma unroll
            for (int ng = 0; ng < NREG / 2; ng++)
                ldm4(bf[ng], bH + swB((uint32_t)(wn * (NREG * 8) + ng * 16 + l15),
                                      (uint32_t)(k16 * 2 + l16)));
#pragma unroll
            for (int mt = 0; mt < 4; mt++)
#pragma unroll
                for (int nt = 0; nt < NREG; nt++)
                    mma16816(c[mt][nt], ah[mt], bf[nt >> 1][nt & 1], bf[nt >> 1][(nt & 1) + 2]);
        }
    }
}

// ---------------- fused MoE kernel (CTA pair per M-tile, N-split) ----------------
__global__ __launch_bounds__(NT, 1)
void k_moe(const float* __restrict__ z, const float* __restrict__ u,
           const float* __restrict__ bz, const float* __restrict__ bhb,
           float* __restrict__ out) {
    const int bt = blockIdx.x >> 1, half = blockIdx.x & 1;
    if (bt >= g_ntiles) return;
    const int e = g_te[bt], start = g_ts[bt], rows = g_tr[bt];
    const int tid = threadIdx.x, lane = tid & 31, warp = tid >> 5;
    const int wm = warp >> 2, wn = warp & 3;
    const int t4 = lane >> 2, t2 = (lane & 3) * 2;

    extern __shared__ char smc[];
    const uint32_t sm0 = s2u(smc);
    const uint32_t aS = sm0 + OAS, a2 = sm0 + OA2, obs = sm0 + OBS;

    __shared__ int ss[TMm];
    if (tid < TMm) ss[tid] = (tid < rows) ? g_perm[start + tid] : -1;
    __syncthreads();

    stage_a32(smc, OAS, z, ss, tid);

    float c[4][8][4];
    int rot = 0;

    // ---- GEMM1 (both halves): a = z @ Wz^T + bz -> a2 smem (fp16) ----
    {
        const __half* Bh = g_Wzh + (size_t)e * Zn * Zn;
        gemm_nc<8>(aS, obs, rot, Bh, c, tid); rot++;
        const float* bzp = bz + (size_t)e * Zn;
#pragma unroll
        for (int mt = 0; mt < 4; mt++) {
            const uint32_t r0 = (uint32_t)(wm * 64 + mt * 16 + t4);
#pragma unroll
            for (int nt = 0; nt < 8; nt++) {
                const int col = wn * 64 + nt * 8 + t2;
                const float2 bb = *(const float2*)(bzp + col);
                const uint32_t u16 = (uint32_t)(wn * 8 + nt);
                *(__half2*)(smc + OA2 + swA(r0, u16) + t2 * 2) =
                    __floats2half2_rn(c[mt][nt][0] + bb.x, c[mt][nt][1] + bb.y);
                *(__half2*)(smc + OA2 + swA(r0 + 8, u16) + t2 * 2) =
                    __floats2half2_rn(c[mt][nt][2] + bb.x, c[mt][nt][3] + bb.y);
            }
        }
    }
    __syncthreads();   // aS free; a2 visible

    stage_a32(smc, OAS, u, ss, tid);

    // ---- GEMM2 (half): h = relu(a @ Wh^T + bh), N in [half*512, half*512+512) ----
    {
        for (int nc = 0; nc < 2; nc++) {
            const int n0 = half * 512 + nc * 256;
            const __half* Bh = g_Whh + ((size_t)e * Hn + n0) * Zn;
            gemm_nc<8>(a2, obs, rot, Bh, c, tid); rot++;
            const float* bhp = bhb + (size_t)e * Hn + n0;
#pragma unroll
            for (int mt = 0; mt < 4; mt++) {
                const int r0 = wm * 64 + mt * 16 + t4;
                const int s0 = ss[r0], s1 = ss[r0 + 8];
#pragma unroll
                for (int nt = 0; nt < 8; nt++) {
                    const int col = wn * 64 + nt * 8 + t2;
                    const float2 bb = *(const float2*)(bhp + col);
                    if (s0 >= 0) {
                        float2 o;
                        o.x = fmaxf(c[mt][nt][0] + bb.x, 0.f);
                        o.y = fmaxf(c[mt][nt][1] + bb.y, 0.f);
                        *(float2*)(out + (size_t)s0 * Hn + n0 + col) = o;
                    }
                    if (s1 >= 0) {
                        float2 o;
                        o.x = fmaxf(c[mt][nt][2] + bb.x, 0.f);
                        o.y = fmaxf(c[mt][nt][3] + bb.y, 0.f);
                        *(float2*)(out + (size_t)s1 * Hn + n0 + col) = o;
                    }
                }
            }
        }
    }

    // ---- GEMM3 (half): v = u @ Wu^T, N in [half*128, half*128+128) ----
    {
        const int n0 = half * 128;
        const __half* Bh = g_Wuh + ((size_t)e * Un + n0) * Zn;
        float* outv = out + (size_t)Bn * Hn;
        gemm_nc<4>(aS, obs, rot, Bh, c, tid); rot++;
#pragma unroll
        for (int mt = 0; mt < 4; mt++) {
            const int r0 = wm * 64 + mt * 16 + t4;
            const int s0 = ss[r0], s1 = ss[r0 + 8];
#pragma unroll
            for (int nt = 0; nt < 4; nt++) {
                const int col = wn * 32 + nt * 8 + t2;
                if (s0 >= 0) {
                    float2 o; o.x = c[mt][nt][0]; o.y = c[mt][nt][1];
                    *(float2*)(outv + (size_t)s0 * Un + n0 + col) = o;
                }
                if (s1 >= 0) {
                    float2 o; o.x = c[mt][nt][2]; o.y = c[mt][nt][3];
                    *(float2*)(outv + (size_t)s1 * Un + n0 + col) = o;
                }
            }
        }
    }
}

// ---------------- launcher ----------------
extern "C" void kernel_launch(void* const* d_in, const int* in_sizes, int n_in,
                              void* d_out, int out_size) {
    (void)in_sizes; (void)n_in; (void)out_size;
    const float* z   = (const float*)d_in[0];
    const float* u   = (const float*)d_in[1];
    const int*   rng = (const int*)d_in[2];
    const float* Wz  = (const float*)d_in[3];
    const float* bz  = (const float*)d_in[4];
    const float* Wh  = (const float*)d_in[5];
    const float* bh  = (const float*)d_in[6];
    const float* Wu  = (const float*)d_in[7];
    float* out = (float*)d_out;

    cudaFuncSetAttribute(k_moe, cudaFuncAttributeMaxDynamicSharedMemorySize, SMEM_DYN);

    k_pre<<<PREBLK + 1, NTPRE>>>(rng, Wz, Wh, Wu);
    k_moe<<<2 * MAXT, NT, SMEM_DYN>>>(z, u, bz, bh, out);
}

// round 9
// speedup vs baseline: 1.0894x; 1.0894x over previous
#include <cuda_runtime.h>
#include <cuda_fp16.h>
#include <cstdint>

#define Bn 8192
#define En 16
#define Zn 256
#define Hn 1024
#define Un 256
#define TM 64                    // M tile
#define MAXT 144
#define NT 256                   // 8 warps
#define NTPRE 512
#define KC 64
#define NC 128                   // N chunk
#define BPART 16384              // B buffer: 128 rows x 128B

// smem byte offsets (XOR-swizzled, no padding)
#define OAS 0                    // z/u tile: 64 x 512B = 32KB
#define OA2 32768                // a tile:   64 x 512B = 32KB
#define OBS 65536                // B ring: 3 x 16KB
#define SMEM_DYN (OBS + 3*BPART) // 114688 (112KB) -> 2 CTAs/SM

// ---------------- device scratch ----------------
__device__ int g_perm[Bn];
__device__ int g_te[MAXT], g_ts[MAXT], g_tr[MAXT];
__device__ int g_ntiles;
__device__ __half g_Wzh[(size_t)En*Zn*Zn];
__device__ __half g_Whh[(size_t)En*Hn*Zn];
__device__ __half g_Wuh[(size_t)En*Un*Un];

// ---------------- helpers ----------------
__device__ __forceinline__ uint32_t s2u(const void* p) {
    uint32_t a;
    asm("{ .reg .u64 t; cvta.to.shared.u64 t, %1; cvt.u32.u64 %0, t; }" : "=r"(a) : "l"(p));
    return a;
}
__device__ __forceinline__ void cpa16(uint32_t dst, const void* src) {
    asm volatile("cp.async.ca.shared.global [%0], [%1], 16;" :: "r"(dst), "l"(src));
}
__device__ __forceinline__ void cpa_commit() { asm volatile("cp.async.commit_group;" ::: "memory"); }
template<int N> __device__ __forceinline__ void cpa_wait() {
    asm volatile("cp.async.wait_group %0;" :: "n"(N) : "memory");
}
__device__ __forceinline__ void ldm4(uint32_t r[4], uint32_t addr) {
    asm volatile("ldmatrix.sync.aligned.m8n8.x4.shared.b16 {%0,%1,%2,%3}, [%4];"
                 : "=r"(r[0]), "=r"(r[1]), "=r"(r[2]), "=r"(r[3]) : "r"(addr));
}
__device__ __forceinline__ void mma16816(float c[4], const uint32_t a[4], uint32_t b0, uint32_t b1) {
    asm volatile("mma.sync.aligned.m16n8k16.row.col.f32.f16.f16.f32 "
                 "{%0,%1,%2,%3}, {%4,%5,%6,%7}, {%8,%9}, {%0,%1,%2,%3};"
                 : "+f"(c[0]), "+f"(c[1]), "+f"(c[2]), "+f"(c[3])
                 : "r"(a[0]), "r"(a[1]), "r"(a[2]), "r"(a[3]), "r"(b0), "r"(b1));
}
// swizzled offsets: A rows 512B (32 16B-units), B rows 128B (8 units)
__device__ __forceinline__ uint32_t swA(uint32_t r, uint32_t c16) {
    return (r << 9) + ((c16 >> 3) << 7) + (((c16 & 7) ^ (r & 7)) << 4);
}
__device__ __forceinline__ uint32_t swB(uint32_t r, uint32_t c16) {
    return (r << 7) + ((c16 ^ (r & 7)) << 4);
}

// ---------------- fused pre-pass: weight cvt + setup ----------------
#define NWz4 (En*Zn*Zn/4)
#define NWh4 (En*Hn*Zn/4)
#define NWu4 (En*Un*Un/4)
#define NW4  (NWz4+NWh4+NWu4)
#define PREBLK (NW4/NTPRE)       // 3072

__global__ __launch_bounds__(NTPRE) void k_pre(const int* __restrict__ rng,
                                               const float* __restrict__ Wz,
                                               const float* __restrict__ Wh,
                                               const float* __restrict__ Wu) {
    if (blockIdx.x == PREBLK) {
        __shared__ int sc[En], soff[En], scur[En];
        const int tid = threadIdx.x, lane = tid & 31;
        if (tid < En) { sc[tid] = 0; scur[tid] = 0; }
        __syncthreads();
        for (int i = tid; i < Bn; i += NTPRE) {
            int e = rng[i];
            unsigned m = __match_any_sync(0xffffffffu, e);
            if (lane == __ffs(m) - 1) atomicAdd(&sc[e], __popc(m));
        }
        __syncthreads();
        if (tid == 0) {
            int acc = 0, nt = 0;
            for (int e = 0; e < En; e++) {
                soff[e] = acc;
                int c = sc[e];
                for (int s = 0; s < c; s += TM) {
                    g_te[nt] = e;
                    g_ts[nt] = acc + s;
                    g_tr[nt] = (c - s) < TM ? (c - s) : TM;
                    nt++;
                }
                acc += c;
            }
            g_ntiles = nt;
        }
        __syncthreads();
        for (int i = tid; i < Bn; i += NTPRE) {
            int e = rng[i];
            unsigned m = __match_any_sync(0xffffffffu, e);
            int leader = __ffs(m) - 1;
            int rank = __popc(m & ((1u << lane) - 1u));
            int base = 0;
            if (lane == leader) base = atomicAdd(&scur[e], __popc(m));
            base = __shfl_sync(0xffffffffu, base, leader);
            g_perm[soff[e] + base + rank] = i;
        }
        return;
    }
    int i = blockIdx.x * NTPRE + threadIdx.x;
    const float* src; __half* dh; int j = i;
    if (j < NWz4)                { src = Wz; dh = g_Wzh; }
    else if ((j -= NWz4) < NWh4) { src = Wh; dh = g_Whh; }
    else { j -= NWh4;              src = Wu; dh = g_Wuh; }
    float4 v = __ldg((const float4*)src + j);
    union { __half2 h[2]; uint2 q; } P;
    P.h[0] = __floats2half2_rn(v.x, v.y);
    P.h[1] = __floats2half2_rn(v.z, v.w);
    ((uint2*)dh)[j] = P.q;
}

// ---------------- A staging: 64 gathered fp32 rows -> fp16 swizzled smem ----------------
__device__ __forceinline__ void stage_a32(char* smc, int off, const float* __restrict__ g,
                                          const int* ss, int tid) {
#pragma unroll
    for (int i = tid; i < TM * 32; i += NT) {
        int r = i >> 5, c16 = i & 31;
        int s = ss[r];
        uint4 q = make_uint4(0u, 0u, 0u, 0u);
        if (s >= 0) {
            const float4 v0 = __ldg((const float4*)(g + (size_t)s * 256 + c16 * 8));
            const float4 v1 = __ldg((const float4*)(g + (size_t)s * 256 + c16 * 8 + 4));
            union { __half2 h[4]; uint4 u; } P;
            P.h[0] = __floats2half2_rn(v0.x, v0.y);
            P.h[1] = __floats2half2_rn(v0.z, v0.w);
            P.h[2] = __floats2half2_rn(v1.x, v1.y);
            P.h[3] = __floats2half2_rn(v1.z, v1.w);
            q = P.u;
        }
        *(uint4*)(smc + off + swA((uint32_t)r, (uint32_t)c16)) = q;
    }
}

// B chunk: 128 rows x 64 halves, swizzled 128B rows
__device__ __forceinline__ void stage_b(uint32_t bbase, const __half* __restrict__ gB,
                                        int kc, int tid) {
#pragma unroll
    for (int i = tid; i < NC * 8; i += NT) {
        int r = i >> 3, c16 = i & 7;
        cpa16(bbase + swB((uint32_t)r, (uint32_t)c16), gB + (size_t)r * 256 + kc * KC + c16 * 8);
    }
}

// ---------------- GEMM: one 64x128 output chunk ----------------
// 8 warps 2x4; warp tile 32x32. 3-buffer B ring rotating across calls (rot).
__device__ __forceinline__ void gemm_nc(uint32_t aB, uint32_t obs, int rot,
                                        const __half* __restrict__ gB,
                                        float c[2][4][4], int tid) {
    const int lane = tid & 31, warp = tid >> 5;
    const int wm = warp >> 2, wn = warp & 3;
    const int l15 = lane & 15, l16 = lane >> 4;

#pragma unroll
    for (int mt = 0; mt < 2; mt++)
#pragma unroll
        for (int nt = 0; nt < 4; nt++)
#pragma unroll
            for (int j = 0; j < 4; j++) c[mt][nt][j] = 0.f;

    stage_b(obs + (uint32_t)(rot % 3) * BPART, gB, 0, tid);
    cpa_commit();

#pragma unroll
    for (int kc = 0; kc < 4; kc++) {
        if (kc < 3) {
            stage_b(obs + (uint32_t)((rot + kc + 1) % 3) * BPART, gB, kc + 1, tid);
            cpa_commit();
            cpa_wait<1>();
        } else {
            cpa_wait<0>();
        }
        __syncthreads();

        const uint32_t bH = obs + (uint32_t)((rot + kc) % 3) * BPART;
#pragma unroll
        for (int k16 = 0; k16 < 4; k16++) {
            const uint32_t ac16 = (uint32_t)(kc * 8 + k16 * 2 + l16);
            uint32_t ah[2][4];
#pragma unroll
            for (int mt = 0; mt < 2; mt++)
                ldm4(ah[mt], aB + swA((uint32_t)(wm * 32 + mt * 16 + l15), ac16));
            uint32_t bf[2][4];
#pragma unroll
            for (int ng = 0; ng < 2; ng++)
                ldm4(bf[ng], bH + swB((uint32_t)(wn * 32 + ng * 16 + l15),
                                      (uint32_t)(k16 * 2 + l16)));
#pragma unroll
            for (int mt = 0; mt < 2; mt++)
#pragma unroll
                for (int nt = 0; nt < 4; nt++)
                    mma16816(c[mt][nt], ah[mt], bf[nt >> 1][nt & 1], bf[nt >> 1][(nt & 1) + 2]);
        }
    }
}

// ---------------- fused MoE kernel (CTA pair per M-tile, N-split) ----------------
__global__ __launch_bounds__(NT, 2)
void k_moe(const float* __restrict__ z, const float* __restrict__ u,
           const float* __restrict__ bz, const float* __restrict__ bhb,
           float* __restrict__ out) {
    const int bt = blockIdx.x >> 1, half = blockIdx.x & 1;
    if (bt >= g_ntiles) return;
    const int e = g_te[bt], start = g_ts[bt], rows = g_tr[bt];
    const int tid = threadIdx.x, lane = tid & 31, warp = tid >> 5;
    const int wm = warp >> 2, wn = warp & 3;
    const int t4 = lane >> 2, t2 = (lane & 3) * 2;

    extern __shared__ char smc[];
    const uint32_t sm0 = s2u(smc);
    const uint32_t aS = sm0 + OAS, a2 = sm0 + OA2, obs = sm0 + OBS;

    __shared__ int ss[TM];
    if (tid < TM) ss[tid] = (tid < rows) ? g_perm[start + tid] : -1;
    __syncthreads();

    stage_a32(smc, OAS, z, ss, tid);

    float c[2][4][4];
    int rot = 0;   // +1 per call (4 chunks ≡ 1 mod 3)

    // ---- GEMM1 (both halves): a = z @ Wz^T + bz -> a2 smem (fp16), 2 chunks ----
    {
        const __half* Bh = g_Wzh + (size_t)e * Zn * Zn;
        for (int nc = 0; nc < 2; nc++) {
            gemm_nc(aS, obs, rot, Bh + (size_t)nc * NC * Zn, c, tid); rot++;
            const float* bzp = bz + (size_t)e * Zn + nc * NC;
#pragma unroll
            for (int mt = 0; mt < 2; mt++) {
                const uint32_t r0 = (uint32_t)(wm * 32 + mt * 16 + t4);
#pragma unroll
                for (int nt = 0; nt < 4; nt++) {
                    const int col = wn * 32 + nt * 8 + t2;
                    const float2 bb = *(const float2*)(bzp + col);
                    const uint32_t u16 = (uint32_t)(nc * 16 + wn * 4 + nt);
                    *(__half2*)(smc + OA2 + swA(r0, u16) + t2 * 2) =
                        __floats2half2_rn(c[mt][nt][0] + bb.x, c[mt][nt][1] + bb.y);
                    *(__half2*)(smc + OA2 + swA(r0 + 8, u16) + t2 * 2) =
                        __floats2half2_rn(c[mt][nt][2] + bb.x, c[mt][nt][3] + bb.y);
                }
            }
        }
    }
    __syncthreads();   // aS free; a2 visible

    stage_a32(smc, OAS, u, ss, tid);

    // ---- GEMM2 (half): h = relu(a @ Wh^T + bh), N in [half*512, half*512+512) ----
    {
        for (int nc = 0; nc < 4; nc++) {
            const int n0 = half * 512 + nc * NC;
            const __half* Bh = g_Whh + ((size_t)e * Hn + n0) * Zn;
            gemm_nc(a2, obs, rot, Bh, c, tid); rot++;
            const float* bhp = bhb + (size_t)e * Hn + n0;
#pragma unroll
            for (int mt = 0; mt < 2; mt++) {
                const int r0 = wm * 32 + mt * 16 + t4;
                const int s0 = ss[r0], s1 = ss[r0 + 8];
#pragma unroll
                for (int nt = 0; nt < 4; nt++) {
                    const int col = wn * 32 + nt * 8 + t2;
                    const float2 bb = *(const float2*)(bhp + col);
                    if (s0 >= 0) {
                        float2 o;
                        o.x = fmaxf(c[mt][nt][0] + bb.x, 0.f);
                        o.y = fmaxf(c[mt][nt][1] + bb.y, 0.f);
                        *(float2*)(out + (size_t)s0 * Hn + n0 + col) = o;
                    }
                    if (s1 >= 0) {
                        float2 o;
                        o.x = fmaxf(c[mt][nt][2] + bb.x, 0.f);
                        o.y = fmaxf(c[mt][nt][3] + bb.y, 0.f);
                        *(float2*)(out + (size_t)s1 * Hn + n0 + col) = o;
                    }
                }
            }
        }
    }

    // ---- GEMM3 (half): v = u @ Wu^T, N in [half*128, half*128+128) ----
    {
        const int n0 = half * NC;
        const __half* Bh = g_Wuh + ((size_t)e * Un + n0) * Zn;
        float* outv = out + (size_t)Bn * Hn;
        gemm_nc(aS, obs, rot, Bh, c, tid); rot++;
#pragma unroll
        for (int mt = 0; mt < 2; mt++) {
            const int r0 = wm * 32 + mt * 16 + t4;
            const int s0 = ss[r0], s1 = ss[r0 + 8];
#pragma unroll
            for (int nt = 0; nt < 4; nt++) {
                const int col = wn * 32 + nt * 8 + t2;
                if (s0 >= 0) {
                    float2 o; o.x = c[mt][nt][0]; o.y = c[mt][nt][1];
                    *(float2*)(outv + (size_t)s0 * Un + n0 + col) = o;
                }
                if (s1 >= 0) {
                    float2 o; o.x = c[mt][nt][2]; o.y = c[mt][nt][3];
                    *(float2*)(outv + (size_t)s1 * Un + n0 + col) = o;
                }
            }
        }
    }
}

// ---------------- launcher ----------------
extern "C" void kernel_launch(void* const* d_in, const int* in_sizes, int n_in,
                              void* d_out, int out_size) {
    (void)in_sizes; (void)n_in; (void)out_size;
    const float* z   = (const float*)d_in[0];
    const float* u   = (const float*)d_in[1];
    const int*   rng = (const int*)d_in[2];
    const float* Wz  = (const float*)d_in[3];
    const float* bz  = (const float*)d_in[4];
    const float* Wh  = (const float*)d_in[5];
    const float* bh  = (const float*)d_in[6];
    const float* Wu  = (const float*)d_in[7];
    float* out = (float*)d_out;

    cudaFuncSetAttribute(k_moe, cudaFuncAttributeMaxDynamicSharedMemorySize, SMEM_DYN);

    k_pre<<<PREBLK + 1, NTPRE>>>(rng, Wz, Wh, Wu);
    k_moe<<<2 * MAXT, NT, SMEM_DYN>>>(z, u, bz, bh, out);
}

// round 10
// speedup vs baseline: 1.2077x; 1.1086x over previous
#include <cuda_runtime.h>
#include <cuda_fp16.h>
#include <cstdint>

#define Bn 8192
#define En 16
#define Zn 256
#define Hn 1024
#define Un 256
#define TM 64
#define MAXT 144
#define NT 512
#define NTPRE 512
#define NC 256                   // N chunk (per gemm call)
#define KC 64                    // K chunk
#define LDA 264                  // A smem row stride (halves)
#define LDB 72                   // B smem row stride (halves)
#define BPART (NC*LDB*2)         // 36864 B per buffer

// smem byte offsets
#define OASH 0
#define OA2H (TM*LDA*2)          // 33792
#define OBS  (2*TM*LDA*2)        // 67584
#define SMEM_DYN (OBS + 3*BPART) // 178176

// ---------------- device scratch ----------------
__device__ int g_perm[Bn];
__device__ int g_te[MAXT], g_ts[MAXT], g_tr[MAXT];
__device__ int g_ntiles;
__device__ __half g_Wzh[(size_t)En*Zn*Zn];
__device__ __half g_Whh[(size_t)En*Hn*Zn];
__device__ __half g_Wuh[(size_t)En*Un*Un];

// ---------------- helpers ----------------
__device__ __forceinline__ uint32_t s2u(const void* p) {
    uint32_t a;
    asm("{ .reg .u64 t; cvta.to.shared.u64 t, %1; cvt.u32.u64 %0, t; }" : "=r"(a) : "l"(p));
    return a;
}
__device__ __forceinline__ void cpa16(uint32_t dst, const void* src) {
    asm volatile("cp.async.ca.shared.global [%0], [%1], 16;" :: "r"(dst), "l"(src));
}
__device__ __forceinline__ void cpa_commit() { asm volatile("cp.async.commit_group;" ::: "memory"); }
template<int N> __device__ __forceinline__ void cpa_wait() {
    asm volatile("cp.async.wait_group %0;" :: "n"(N) : "memory");
}
__device__ __forceinline__ void ldm4(uint32_t r[4], uint32_t addr) {
    asm volatile("ldmatrix.sync.aligned.m8n8.x4.shared.b16 {%0,%1,%2,%3}, [%4];"
                 : "=r"(r[0]), "=r"(r[1]), "=r"(r[2]), "=r"(r[3]) : "r"(addr));
}
__device__ __forceinline__ void mma16816(float c[4], const uint32_t a[4], uint32_t b0, uint32_t b1) {
    asm volatile("mma.sync.aligned.m16n8k16.row.col.f32.f16.f16.f32 "
                 "{%0,%1,%2,%3}, {%4,%5,%6,%7}, {%8,%9}, {%0,%1,%2,%3};"
                 : "+f"(c[0]), "+f"(c[1]), "+f"(c[2]), "+f"(c[3])
                 : "r"(a[0]), "r"(a[1]), "r"(a[2]), "r"(a[3]), "r"(b0), "r"(b1));
}

// ---------------- fused pre-pass: weight cvt + setup ----------------
#define NWz4 (En*Zn*Zn/4)
#define NWh4 (En*Hn*Zn/4)
#define NWu4 (En*Un*Un/4)
#define NW4  (NWz4+NWh4+NWu4)
#define PREBLK (NW4/NTPRE)       // 3072

__global__ __launch_bounds__(NTPRE) void k_pre(const int* __restrict__ rng,
                                               const float* __restrict__ Wz,
                                               const float* __restrict__ Wh,
                                               const float* __restrict__ Wu) {
    if (blockIdx.x == PREBLK) {
        __shared__ int sc[En], soff[En], scur[En];
        const int tid = threadIdx.x, lane = tid & 31;
        if (tid < En) { sc[tid] = 0; scur[tid] = 0; }
        __syncthreads();
        for (int i = tid; i < Bn; i += NTPRE) {
            int e = rng[i];
            unsigned m = __match_any_sync(0xffffffffu, e);
            if (lane == __ffs(m) - 1) atomicAdd(&sc[e], __popc(m));
        }
        __syncthreads();
        if (tid == 0) {
            int acc = 0, nt = 0;
            for (int e = 0; e < En; e++) {
                soff[e] = acc;
                int c = sc[e];
                for (int s = 0; s < c; s += TM) {
                    g_te[nt] = e;
                    g_ts[nt] = acc + s;
                    g_tr[nt] = (c - s) < TM ? (c - s) : TM;
                    nt++;
                }
                acc += c;
            }
            g_ntiles = nt;
        }
        __syncthreads();
        for (int i = tid; i < Bn; i += NTPRE) {
            int e = rng[i];
            unsigned m = __match_any_sync(0xffffffffu, e);
            int leader = __ffs(m) - 1;
            int rank = __popc(m & ((1u << lane) - 1u));
            int base = 0;
            if (lane == leader) base = atomicAdd(&scur[e], __popc(m));
            base = __shfl_sync(0xffffffffu, base, leader);
            g_perm[soff[e] + base + rank] = i;
        }
        return;
    }
    int i = blockIdx.x * NTPRE + threadIdx.x;
    const float* src; __half* dh; int j = i;
    if (j < NWz4)                { src = Wz; dh = g_Wzh; }
    else if ((j -= NWz4) < NWh4) { src = Wh; dh = g_Whh; }
    else { j -= NWh4;              src = Wu; dh = g_Wuh; }
    float4 v = __ldg((const float4*)src + j);
    union { __half2 h[2]; uint2 q; } P;
    P.h[0] = __floats2half2_rn(v.x, v.y);
    P.h[1] = __floats2half2_rn(v.z, v.w);
    ((uint2*)dh)[j] = P.q;
}

// ---------------- A staging: gathered fp32 rows -> fp16 smem ----------------
__device__ __forceinline__ void stage_a32(char* smc, int off, const float* __restrict__ g,
                                          const int* ss, int tid) {
#pragma unroll
    for (int i = tid; i < TM * 32; i += NT) {
        int r = i >> 5, c = (i & 31) << 3;
        int s = ss[r];
        uint4 q = make_uint4(0u, 0u, 0u, 0u);
        if (s >= 0) {
            const float4 v0 = __ldg((const float4*)(g + (size_t)s * 256 + c));
            const float4 v1 = __ldg((const float4*)(g + (size_t)s * 256 + c + 4));
            union { __half2 h[4]; uint4 u; } P;
            P.h[0] = __floats2half2_rn(v0.x, v0.y);
            P.h[1] = __floats2half2_rn(v0.z, v0.w);
            P.h[2] = __floats2half2_rn(v1.x, v1.y);
            P.h[3] = __floats2half2_rn(v1.z, v1.w);
            q = P.u;
        }
        *(uint4*)(smc + off + (uint32_t)(r * LDA + c) * 2) = q;
    }
}

// B chunk: NC rows x 64 halves via cp.async
__device__ __forceinline__ void stage_b(uint32_t bh, const __half* __restrict__ gh, int kc, int tid) {
#pragma unroll
    for (int i = tid; i < NC * 8; i += NT) {
        int r = i >> 3, c = (i & 7) << 3;
        cpa16(bh + (uint32_t)(r * LDB + c) * 2, gh + (size_t)r * 256 + kc * KC + c);
    }
}

// ---------------- GEMM: one 64x256 output chunk, fp16 ----------------
// Warp tile 32x32; 16 warps 2x8. Caller guarantees this call's K-chunk 0 is
// already staged+committed into buffer rot%3. At the final K-chunk this call
// prestages gBnext's chunk 0 into buffer (rot+4)%3 (continuous pipeline).
// Inner loop double-buffers ldmatrix fragments (prefetch k16+1 during k16 MMAs).
__device__ __forceinline__ void gemm_nc(uint32_t aB, uint32_t obs, int rot,
                                        const __half* __restrict__ gB,
                                        const __half* __restrict__ gBnext,
                                        float c[2][4][4], int tid) {
    const int lane = tid & 31, warp = tid >> 5;
    const int wm = warp >> 3, wn = warp & 7;
    const int lrow = (lane & 7) + ((lane >> 3) & 1) * 8;
    const int lk8  = (lane >> 4) * 8;

#pragma unroll
    for (int mt = 0; mt < 2; mt++)
#pragma unroll
        for (int nt = 0; nt < 4; nt++)
#pragma unroll
            for (int j = 0; j < 4; j++) c[mt][nt][j] = 0.f;

#pragma unroll
    for (int kc = 0; kc < 4; kc++) {
        const __half* nsrc = (kc < 3) ? gB : gBnext;
        if (nsrc) {
            stage_b(obs + (uint32_t)((rot + kc + 1) % 3) * BPART, nsrc, (kc < 3) ? kc + 1 : 0, tid);
            cpa_commit();
            cpa_wait<1>();
        } else {
            cpa_wait<0>();
        }
        __syncthreads();

        const uint32_t bH = obs + (uint32_t)((rot + kc) % 3) * BPART;
        uint32_t ah[2][2][4], bf[2][2][4];
        // preload k16 = 0
        {
            const int ka = kc * KC + lk8;
#pragma unroll
            for (int mt = 0; mt < 2; mt++)
                ldm4(ah[0][mt], aB + (uint32_t)((wm * 32 + mt * 16 + lrow) * LDA + ka) * 2);
#pragma unroll
            for (int ng = 0; ng < 2; ng++)
                ldm4(bf[0][ng], bH + (uint32_t)((wn * 32 + ng * 16 + lrow) * LDB + lk8) * 2);
        }
#pragma unroll
        for (int k16 = 0; k16 < 4; k16++) {
            const int cur = k16 & 1, nxt = cur ^ 1;
            if (k16 < 3) {
                const int ka = kc * KC + (k16 + 1) * 16 + lk8;
#pragma unroll
                for (int mt = 0; mt < 2; mt++)
                    ldm4(ah[nxt][mt], aB + (uint32_t)((wm * 32 + mt * 16 + lrow) * LDA + ka) * 2);
#pragma unroll
                for (int ng = 0; ng < 2; ng++)
                    ldm4(bf[nxt][ng], bH + (uint32_t)((wn * 32 + ng * 16 + lrow) * LDB + (k16 + 1) * 16 + lk8) * 2);
            }
#pragma unroll
            for (int mt = 0; mt < 2; mt++)
#pragma unroll
                for (int nt = 0; nt < 4; nt++)
                    mma16816(c[mt][nt], ah[cur][mt], bf[cur][nt >> 1][nt & 1],
                             bf[cur][nt >> 1][(nt & 1) + 2]);
        }
    }
}

// ---------------- fused MoE kernel ----------------
__global__ __launch_bounds__(NT, 1)
void k_moe(const float* __restrict__ z, const float* __restrict__ u,
           const float* __restrict__ bz, const float* __restrict__ bhb,
           float* __restrict__ out) {
    const int bt = blockIdx.x;
    if (bt >= g_ntiles) return;
    const int e = g_te[bt], start = g_ts[bt], rows = g_tr[bt];
    const int tid = threadIdx.x, lane = tid & 31, warp = tid >> 5;
    const int wm = warp >> 3, wn = warp & 7;
    const int t4 = lane >> 2, t2 = (lane & 3) * 2;

    extern __shared__ char smc[];
    const uint32_t sm0 = s2u(smc);
    const uint32_t aSH = sm0 + OASH, a2H = sm0 + OA2H, obs = sm0 + OBS;

    __shared__ int ss[TM];
    if (tid < TM) ss[tid] = (tid < rows) ? g_perm[start + tid] : -1;
    __syncthreads();

    const __half* Wze = g_Wzh + (size_t)e * Zn * Zn;
    const __half* Whe = g_Whh + (size_t)e * Hn * Zn;
    const __half* Wue = g_Wuh + (size_t)e * Un * Un;

    // prestage GEMM1 chunk 0 so its flight overlaps the synchronous z gather
    stage_b(obs, Wze, 0, tid);
    cpa_commit();

    stage_a32(smc, OASH, z, ss, tid);

    float c[2][4][4];

    // ---- GEMM1: a = z @ Wz^T + bz -> a2H smem (fp16), N=256, rot=0 ----
    {
        gemm_nc(aSH, obs, 0, Wze, Whe /* next: GEMM2 nc0 */, c, tid);
        const float* bzp = bz + (size_t)e * Zn;
#pragma unroll
        for (int mt = 0; mt < 2; mt++) {
            const int r0 = wm * 32 + mt * 16 + t4;
#pragma unroll
            for (int nt = 0; nt < 4; nt++) {
                const int col = wn * 32 + nt * 8 + t2;
                const float2 bb = *(const float2*)(bzp + col);
                uint32_t o = (uint32_t)(r0 * LDA + col) * 2;
                *(__half2*)(smc + OA2H + o) = __floats2half2_rn(c[mt][nt][0] + bb.x, c[mt][nt][1] + bb.y);
                o = (uint32_t)((r0 + 8) * LDA + col) * 2;
                *(__half2*)(smc + OA2H + o) = __floats2half2_rn(c[mt][nt][2] + bb.x, c[mt][nt][3] + bb.y);
            }
        }
    }
    __syncthreads();   // aSH free for u; a2H visible

    stage_a32(smc, OASH, u, ss, tid);

    // ---- GEMM2: h = relu(a @ Wh^T + bh) -> out, 4 chunks of N=256, rot=1..4 ----
    {
        for (int nc = 0; nc < 4; nc++) {
            const __half* nxt = (nc < 3) ? (Whe + (size_t)(nc + 1) * NC * Zn) : Wue;
            gemm_nc(a2H, obs, 1 + nc, Whe + (size_t)nc * NC * Zn, nxt, c, tid);
            const float* bhp = bhb + (size_t)e * Hn + nc * NC;
#pragma unroll
            for (int mt = 0; mt < 2; mt++) {
                const int r0 = wm * 32 + mt * 16 + t4;
                const int s0 = ss[r0], s1 = ss[r0 + 8];
#pragma unroll
                for (int nt = 0; nt < 4; nt++) {
                    const int col = wn * 32 + nt * 8 + t2;
                    const float2 bb = *(const float2*)(bhp + col);
                    if (s0 >= 0) {
                        float2 o;
                        o.x = fmaxf(c[mt][nt][0] + bb.x, 0.f);
                        o.y = fmaxf(c[mt][nt][1] + bb.y, 0.f);
                        *(float2*)(out + (size_t)s0 * Hn + nc * NC + col) = o;
                    }
                    if (s1 >= 0) {
                        float2 o;
                        o.x = fmaxf(c[mt][nt][2] + bb.x, 0.f);
                        o.y = fmaxf(c[mt][nt][3] + bb.y, 0.f);
                        *(float2*)(out + (size_t)s1 * Hn + nc * NC + col) = o;
                    }
                }
            }
        }
    }

    // ---- GEMM3: v = u @ Wu^T -> out + Bn*Hn, N=256, rot=5 ----
    {
        float* outv = out + (size_t)Bn * Hn;
        gemm_nc(aSH, obs, 5, Wue, nullptr, c, tid);
#pragma unroll
        for (int mt = 0; mt < 2; mt++) {
            const int r0 = wm * 32 + mt * 16 + t4;
            const int s0 = ss[r0], s1 = ss[r0 + 8];
#pragma unroll
            for (int nt = 0; nt < 4; nt++) {
                const int col = wn * 32 + nt * 8 + t2;
                if (s0 >= 0) {
                    float2 o; o.x = c[mt][nt][0]; o.y = c[mt][nt][1];
                    *(float2*)(outv + (size_t)s0 * Un + col) = o;
                }
                if (s1 >= 0) {
                    float2 o; o.x = c[mt][nt][2]; o.y = c[mt][nt][3];
                    *(float2*)(outv + (size_t)s1 * Un + col) = o;
                }
            }
        }
    }
}

// ---------------- launcher ----------------
extern "C" void kernel_launch(void* const* d_in, const int* in_sizes, int n_in,
                              void* d_out, int out_size) {
    (void)in_sizes; (void)n_in; (void)out_size;
    const float* z   = (const float*)d_in[0];
    const float* u   = (const float*)d_in[1];
    const int*   rng = (const int*)d_in[2];
    const float* Wz  = (const float*)d_in[3];
    const float* bz  = (const float*)d_in[4];
    const float* Wh  = (const float*)d_in[5];
    const float* bh  = (const float*)d_in[6];
    const float* Wu  = (const float*)d_in[7];
    float* out = (float*)d_out;

    cudaFuncSetAttribute(k_moe, cudaFuncAttributeMaxDynamicSharedMemorySize, SMEM_DYN);

    k_pre<<<PREBLK + 1, NTPRE>>>(rng, Wz, Wh, Wu);
    k_moe<<<MAXT, NT, SMEM_DYN>>>(z, u, bz, bh, out);
}

// round 11
// speedup vs baseline: 1.2117x; 1.0033x over previous
#include <cuda_runtime.h>
#include <cuda_fp16.h>
#include <cstdint>

#define Bn 8192
#define En 16
#define Zn 256
#define Hn 1024
#define Un 256
#define TM 64
#define MAXT 144
#define NT 512
#define NTPRE 512
#define NC 256                   // N chunk (per gemm call)
#define KC 64                    // K chunk
#define LDA 264                  // A smem row stride (halves)
#define LDB 72                   // B smem row stride (halves)
#define BPART (NC*LDB*2)         // 36864 B per buffer

// smem byte offsets
#define OASH 0
#define OA2H (TM*LDA*2)          // 33792
#define OBS  (2*TM*LDA*2)        // 67584
#define SMEM_DYN (OBS + 4*BPART) // 215040 (210KB)

// ---------------- device scratch ----------------
__device__ int g_perm[Bn];
__device__ int g_te[MAXT], g_ts[MAXT], g_tr[MAXT];
__device__ int g_ntiles;
__device__ __half g_Wzh[(size_t)En*Zn*Zn];
__device__ __half g_Whh[(size_t)En*Hn*Zn];
__device__ __half g_Wuh[(size_t)En*Un*Un];

// ---------------- helpers ----------------
__device__ __forceinline__ uint32_t s2u(const void* p) {
    uint32_t a;
    asm("{ .reg .u64 t; cvta.to.shared.u64 t, %1; cvt.u32.u64 %0, t; }" : "=r"(a) : "l"(p));
    return a;
}
__device__ __forceinline__ void cpa16(uint32_t dst, const void* src) {
    asm volatile("cp.async.ca.shared.global [%0], [%1], 16;" :: "r"(dst), "l"(src));
}
__device__ __forceinline__ void cpa_commit() { asm volatile("cp.async.commit_group;" ::: "memory"); }
template<int N> __device__ __forceinline__ void cpa_wait() {
    asm volatile("cp.async.wait_group %0;" :: "n"(N) : "memory");
}
__device__ __forceinline__ void ldm4(uint32_t r[4], uint32_t addr) {
    asm volatile("ldmatrix.sync.aligned.m8n8.x4.shared.b16 {%0,%1,%2,%3}, [%4];"
                 : "=r"(r[0]), "=r"(r[1]), "=r"(r[2]), "=r"(r[3]) : "r"(addr));
}
__device__ __forceinline__ void mma16816(float c[4], const uint32_t a[4], uint32_t b0, uint32_t b1) {
    asm volatile("mma.sync.aligned.m16n8k16.row.col.f32.f16.f16.f32 "
                 "{%0,%1,%2,%3}, {%4,%5,%6,%7}, {%8,%9}, {%0,%1,%2,%3};"
                 : "+f"(c[0]), "+f"(c[1]), "+f"(c[2]), "+f"(c[3])
                 : "r"(a[0]), "r"(a[1]), "r"(a[2]), "r"(a[3]), "r"(b0), "r"(b1));
}

// ---------------- fused pre-pass: weight cvt (MLP=2) + setup ----------------
#define NWz4 (En*Zn*Zn/4)
#define NWh4 (En*Hn*Zn/4)
#define NWu4 (En*Un*Un/4)
#define NW4  (NWz4+NWh4+NWu4)        // 1572864
#define PREBLK (NW4/(NTPRE*2))       // 1536

__device__ __forceinline__ void cvt_one(int j, const float* __restrict__ Wz,
                                        const float* __restrict__ Wh,
                                        const float* __restrict__ Wu) {
    const float* src; __half* dh;
    if (j < NWz4)                { src = Wz; dh = g_Wzh; }
    else if ((j -= NWz4) < NWh4) { src = Wh; dh = g_Whh; }
    else { j -= NWh4;              src = Wu; dh = g_Wuh; }
    float4 v = __ldg((const float4*)src + j);
    union { __half2 h[2]; uint2 q; } P;
    P.h[0] = __floats2half2_rn(v.x, v.y);
    P.h[1] = __floats2half2_rn(v.z, v.w);
    ((uint2*)dh)[j] = P.q;
}

__global__ __launch_bounds__(NTPRE) void k_pre(const int* __restrict__ rng,
                                               const float* __restrict__ Wz,
                                               const float* __restrict__ Wh,
                                               const float* __restrict__ Wu) {
    if (blockIdx.x == PREBLK) {
        __shared__ int sc[En], soff[En], scur[En];
        const int tid = threadIdx.x, lane = tid & 31;
        if (tid < En) { sc[tid] = 0; scur[tid] = 0; }
        __syncthreads();
        for (int i = tid; i < Bn; i += NTPRE) {
            int e = rng[i];
            unsigned m = __match_any_sync(0xffffffffu, e);
            if (lane == __ffs(m) - 1) atomicAdd(&sc[e], __popc(m));
        }
        __syncthreads();
        if (tid == 0) {
            int acc = 0, nt = 0;
            for (int e = 0; e < En; e++) {
                soff[e] = acc;
                int c = sc[e];
                for (int s = 0; s < c; s += TM) {
                    g_te[nt] = e;
                    g_ts[nt] = acc + s;
                    g_tr[nt] = (c - s) < TM ? (c - s) : TM;
                    nt++;
                }
                acc += c;
            }
            g_ntiles = nt;
        }
        __syncthreads();
        for (int i = tid; i < Bn; i += NTPRE) {
            int e = rng[i];
            unsigned m = __match_any_sync(0xffffffffu, e);
            int leader = __ffs(m) - 1;
            int rank = __popc(m & ((1u << lane) - 1u));
            int base = 0;
            if (lane == leader) base = atomicAdd(&scur[e], __popc(m));
            base = __shfl_sync(0xffffffffu, base, leader);
            g_perm[soff[e] + base + rank] = i;
        }
        return;
    }
    const int i0 = blockIdx.x * (NTPRE * 2) + threadIdx.x;
    cvt_one(i0, Wz, Wh, Wu);
    cvt_one(i0 + NTPRE, Wz, Wh, Wu);
}

// ---------------- A staging: gathered fp32 rows -> fp16 smem ----------------
__device__ __forceinline__ void stage_a32(char* smc, int off, const float* __restrict__ g,
                                          const int* ss, int tid) {
#pragma unroll
    for (int i = tid; i < TM * 32; i += NT) {
        int r = i >> 5, c = (i & 31) << 3;
        int s = ss[r];
        uint4 q = make_uint4(0u, 0u, 0u, 0u);
        if (s >= 0) {
            const float4 v0 = __ldg((const float4*)(g + (size_t)s * 256 + c));
            const float4 v1 = __ldg((const float4*)(g + (size_t)s * 256 + c + 4));
            union { __half2 h[4]; uint4 u; } P;
            P.h[0] = __floats2half2_rn(v0.x, v0.y);
            P.h[1] = __floats2half2_rn(v0.z, v0.w);
            P.h[2] = __floats2half2_rn(v1.x, v1.y);
            P.h[3] = __floats2half2_rn(v1.z, v1.w);
            q = P.u;
        }
        *(uint4*)(smc + off + (uint32_t)(r * LDA + c) * 2) = q;
    }
}

// B chunk: NC rows x 64 halves via cp.async
__device__ __forceinline__ void stage_b(uint32_t bh, const __half* __restrict__ gh, int kc, int tid) {
#pragma unroll
    for (int i = tid; i < NC * 8; i += NT) {
        int r = i >> 3, c = (i & 7) << 3;
        cpa16(bh + (uint32_t)(r * LDB + c) * 2, gh + (size_t)r * 256 + kc * KC + c);
    }
}

// ---------------- GEMM: one 64x256 output chunk, fp16 ----------------
// Warp tile 32x32; 16 warps 2x8. 4-buffer ring, buffer = chunk index (kc).
// ENTRY INVARIANT: this call's chunks 0 and 1 are staged+committed (2 groups
// pending). Each iteration kc stages chunk kc+2 (kc<2: this GEMM; kc>=2:
// gBnext's chunk kc-2), keeping 3 groups in flight; wait_group<2> retires the
// oldest => chunk kc has arrived. Exit invariant: next call's chunks 0,1 pending.
// gBnext==nullptr (final call) drains: wait<1> at kc=2, wait<0> at kc=3.
__device__ __forceinline__ void gemm_nc(uint32_t aB, uint32_t obs,
                                        const __half* __restrict__ gB,
                                        const __half* __restrict__ gBnext,
                                        float c[2][4][4], int tid) {
    const int lane = tid & 31, warp = tid >> 5;
    const int wm = warp >> 3, wn = warp & 7;
    const int lrow = (lane & 7) + ((lane >> 3) & 1) * 8;
    const int lk8  = (lane >> 4) * 8;

#pragma unroll
    for (int mt = 0; mt < 2; mt++)
#pragma unroll
        for (int nt = 0; nt < 4; nt++)
#pragma unroll
            for (int j = 0; j < 4; j++) c[mt][nt][j] = 0.f;

#pragma unroll
    for (int kc = 0; kc < 4; kc++) {
        const __half* nsrc = (kc < 2) ? gB : gBnext;
        if (nsrc) {
            stage_b(obs + (uint32_t)((kc + 2) & 3) * BPART, nsrc, (kc < 2) ? kc + 2 : kc - 2, tid);
            cpa_commit();
            cpa_wait<2>();
        } else {
            if (kc == 2) cpa_wait<1>(); else cpa_wait<0>();
        }
        __syncthreads();

        const uint32_t bH = obs + (uint32_t)kc * BPART;
        uint32_t ah[2][2][4], bf[2][2][4];
        {
            const int ka = kc * KC + lk8;
#pragma unroll
            for (int mt = 0; mt < 2; mt++)
                ldm4(ah[0][mt], aB + (uint32_t)((wm * 32 + mt * 16 + lrow) * LDA + ka) * 2);
#pragma unroll
            for (int ng = 0; ng < 2; ng++)
                ldm4(bf[0][ng], bH + (uint32_t)((wn * 32 + ng * 16 + lrow) * LDB + lk8) * 2);
        }
#pragma unroll
        for (int k16 = 0; k16 < 4; k16++) {
            const int cur = k16 & 1, nxt = cur ^ 1;
            if (k16 < 3) {
                const int ka = kc * KC + (k16 + 1) * 16 + lk8;
#pragma unroll
                for (int mt = 0; mt < 2; mt++)
                    ldm4(ah[nxt][mt], aB + (uint32_t)((wm * 32 + mt * 16 + lrow) * LDA + ka) * 2);
#pragma unroll
                for (int ng = 0; ng < 2; ng++)
                    ldm4(bf[nxt][ng], bH + (uint32_t)((wn * 32 + ng * 16 + lrow) * LDB + (k16 + 1) * 16 + lk8) * 2);
            }
#pragma unroll
            for (int mt = 0; mt < 2; mt++)
#pragma unroll
                for (int nt = 0; nt < 4; nt++)
                    mma16816(c[mt][nt], ah[cur][mt], bf[cur][nt >> 1][nt & 1],
                             bf[cur][nt >> 1][(nt & 1) + 2]);
        }
    }
}

// ---------------- fused MoE kernel ----------------
__global__ __launch_bounds__(NT, 1)
void k_moe(const float* __restrict__ z, const float* __restrict__ u,
           const float* __restrict__ bz, const float* __restrict__ bhb,
           float* __restrict__ out) {
    const int bt = blockIdx.x;
    if (bt >= g_ntiles) return;
    const int e = g_te[bt], start = g_ts[bt], rows = g_tr[bt];
    const int tid = threadIdx.x, lane = tid & 31, warp = tid >> 5;
    const int wm = warp >> 3, wn = warp & 7;
    const int t4 = lane >> 2, t2 = (lane & 3) * 2;

    extern __shared__ char smc[];
    const uint32_t sm0 = s2u(smc);
    const uint32_t aSH = sm0 + OASH, a2H = sm0 + OA2H, obs = sm0 + OBS;

    __shared__ int ss[TM];
    if (tid < TM) ss[tid] = (tid < rows) ? g_perm[start + tid] : -1;
    __syncthreads();

    const __half* Wze = g_Wzh + (size_t)e * Zn * Zn;
    const __half* Whe = g_Whh + (size_t)e * Hn * Zn;
    const __half* Wue = g_Wuh + (size_t)e * Un * Un;

    // prologue: establish 2-deep pipeline, overlapping the synchronous z gather
    stage_b(obs, Wze, 0, tid);
    cpa_commit();
    stage_b(obs + BPART, Wze, 1, tid);
    cpa_commit();

    stage_a32(smc, OASH, z, ss, tid);

    float c[2][4][4];

    // ---- GEMM1: a = z @ Wz^T + bz -> a2H smem (fp16), N=256 ----
    {
        gemm_nc(aSH, obs, Wze, Whe /* next: GEMM2 nc0 */, c, tid);
        const float* bzp = bz + (size_t)e * Zn;
#pragma unroll
        for (int mt = 0; mt < 2; mt++) {
            const int r0 = wm * 32 + mt * 16 + t4;
#pragma unroll
            for (int nt = 0; nt < 4; nt++) {
                const int col = wn * 32 + nt * 8 + t2;
                const float2 bb = *(const float2*)(bzp + col);
                uint32_t o = (uint32_t)(r0 * LDA + col) * 2;
                *(__half2*)(smc + OA2H + o) = __floats2half2_rn(c[mt][nt][0] + bb.x, c[mt][nt][1] + bb.y);
                o = (uint32_t)((r0 + 8) * LDA + col) * 2;
                *(__half2*)(smc + OA2H + o) = __floats2half2_rn(c[mt][nt][2] + bb.x, c[mt][nt][3] + bb.y);
            }
        }
    }
    __syncthreads();   // aSH free for u; a2H visible

    stage_a32(smc, OASH, u, ss, tid);

    // ---- GEMM2: h = relu(a @ Wh^T + bh) -> out, 4 chunks of N=256 ----
    {
        for (int nc = 0; nc < 4; nc++) {
            const __half* nxt = (nc < 3) ? (Whe + (size_t)(nc + 1) * NC * Zn) : Wue;
            gemm_nc(a2H, obs, Whe + (size_t)nc * NC * Zn, nxt, c, tid);
            const float* bhp = bhb + (size_t)e * Hn + nc * NC;
#pragma unroll
            for (int mt = 0; mt < 2; mt++) {
                const int r0 = wm * 32 + mt * 16 + t4;
                const int s0 = ss[r0], s1 = ss[r0 + 8];
#pragma unroll
                for (int nt = 0; nt < 4; nt++) {
                    const int col = wn * 32 + nt * 8 + t2;
                    const float2 bb = *(const float2*)(bhp + col);
                    if (s0 >= 0) {
                        float2 o;
                        o.x = fmaxf(c[mt][nt][0] + bb.x, 0.f);
                        o.y = fmaxf(c[mt][nt][1] + bb.y, 0.f);
                        *(float2*)(out + (size_t)s0 * Hn + nc * NC + col) = o;
                    }
                    if (s1 >= 0) {
                        float2 o;
                        o.x = fmaxf(c[mt][nt][2] + bb.x, 0.f);
                        o.y = fmaxf(c[mt][nt][3] + bb.y, 0.f);
                        *(float2*)(out + (size_t)s1 * Hn + nc * NC + col) = o;
                    }
                }
            }
        }
    }

    // ---- GEMM3: v = u @ Wu^T -> out + Bn*Hn, N=256, final (drain) ----
    {
        float* outv = out + (size_t)Bn * Hn;
        gemm_nc(aSH, obs, Wue, nullptr, c, tid);
#pragma unroll
        for (int mt = 0; mt < 2; mt++) {
            const int r0 = wm * 32 + mt * 16 + t4;
            const int s0 = ss[r0], s1 = ss[r0 + 8];
#pragma unroll
            for (int nt = 0; nt < 4; nt++) {
                const int col = wn * 32 + nt * 8 + t2;
                if (s0 >= 0) {
                    float2 o; o.x = c[mt][nt][0]; o.y = c[mt][nt][1];
                    *(float2*)(outv + (size_t)s0 * Un + col) = o;
                }
                if (s1 >= 0) {
                    float2 o; o.x = c[mt][nt][2]; o.y = c[mt][nt][3];
                    *(float2*)(outv + (size_t)s1 * Un + col) = o;
                }
            }
        }
    }
}

// ---------------- launcher ----------------
extern "C" void kernel_launch(void* const* d_in, const int* in_sizes, int n_in,
                              void* d_out, int out_size) {
    (void)in_sizes; (void)n_in; (void)out_size;
    const float* z   = (const float*)d_in[0];
    const float* u   = (const float*)d_in[1];
    const int*   rng = (const int*)d_in[2];
    const float* Wz  = (const float*)d_in[3];
    const float* bz  = (const float*)d_in[4];
    const float* Wh  = (const float*)d_in[5];
    const float* bh  = (const float*)d_in[6];
    const float* Wu  = (const float*)d_in[7];
    float* out = (float*)d_out;

    cudaFuncSetAttribute(k_moe, cudaFuncAttributeMaxDynamicSharedMemorySize, SMEM_DYN);

    k_pre<<<PREBLK + 1, NTPRE>>>(rng, Wz, Wh, Wu);
    k_moe<<<MAXT, NT, SMEM_DYN>>>(z, u, bz, bh, out);
}

// round 12
// speedup vs baseline: 1.2393x; 1.0228x over previous
#include <cuda_runtime.h>
#include <cuda_fp16.h>
#include <cstdint>

#define Bn 8192
#define En 16
#define Zn 256
#define Hn 1024
#define Un 256
#define TM 64
#define MAXT 144
#define NT 512
#define NTPRE 512
#define NCG 128                  // N chunk per group (per gemm call)
#define KC 64                    // K chunk
#define LDA 264                  // A smem row stride (halves)
#define LDB 72                   // B smem row stride (halves)
#define BPART (NCG*LDB*2)        // 18432 B per buffer

// smem byte offsets
#define OASH 0
#define OA2H (TM*LDA*2)          // 33792
#define OBS  (2*TM*LDA*2)        // 67584
#define SMEM_DYN (OBS + 6*BPART) // 178176 (per-group rings: g*3*BPART)

// ---------------- device scratch ----------------
__device__ int g_perm[Bn];
__device__ int g_te[MAXT], g_ts[MAXT], g_tr[MAXT];
__device__ int g_ntiles;
__device__ __half g_Wzh[(size_t)En*Zn*Zn];
__device__ __half g_Whh[(size_t)En*Hn*Zn];
__device__ __half g_Wuh[(size_t)En*Un*Un];

// ---------------- helpers ----------------
__device__ __forceinline__ uint32_t s2u(const void* p) {
    uint32_t a;
    asm("{ .reg .u64 t; cvta.to.shared.u64 t, %1; cvt.u32.u64 %0, t; }" : "=r"(a) : "l"(p));
    return a;
}
__device__ __forceinline__ void cpa16(uint32_t dst, const void* src) {
    asm volatile("cp.async.ca.shared.global [%0], [%1], 16;" :: "r"(dst), "l"(src));
}
__device__ __forceinline__ void cpa_commit() { asm volatile("cp.async.commit_group;" ::: "memory"); }
template<int N> __device__ __forceinline__ void cpa_wait() {
    asm volatile("cp.async.wait_group %0;" :: "n"(N) : "memory");
}
__device__ __forceinline__ void gbar(int id) {   // group-scoped named barrier (256 threads)
    asm volatile("bar.sync %0, 256;" :: "r"(id) : "memory");
}
__device__ __forceinline__ void ldm4(uint32_t r[4], uint32_t addr) {
    asm volatile("ldmatrix.sync.aligned.m8n8.x4.shared.b16 {%0,%1,%2,%3}, [%4];"
                 : "=r"(r[0]), "=r"(r[1]), "=r"(r[2]), "=r"(r[3]) : "r"(addr));
}
__device__ __forceinline__ void mma16816(float c[4], const uint32_t a[4], uint32_t b0, uint32_t b1) {
    asm volatile("mma.sync.aligned.m16n8k16.row.col.f32.f16.f16.f32 "
                 "{%0,%1,%2,%3}, {%4,%5,%6,%7}, {%8,%9}, {%0,%1,%2,%3};"
                 : "+f"(c[0]), "+f"(c[1]), "+f"(c[2]), "+f"(c[3])
                 : "r"(a[0]), "r"(a[1]), "r"(a[2]), "r"(a[3]), "r"(b0), "r"(b1));
}

// ---------------- fused pre-pass: weight cvt (MLP=2) + setup ----------------
#define NWz4 (En*Zn*Zn/4)
#define NWh4 (En*Hn*Zn/4)
#define NWu4 (En*Un*Un/4)
#define NW4  (NWz4+NWh4+NWu4)
#define PREBLK (NW4/(NTPRE*2))       // 1536

__device__ __forceinline__ void cvt_one(int j, const float* __restrict__ Wz,
                                        const float* __restrict__ Wh,
                                        const float* __restrict__ Wu) {
    const float* src; __half* dh;
    if (j < NWz4)                { src = Wz; dh = g_Wzh; }
    else if ((j -= NWz4) < NWh4) { src = Wh; dh = g_Whh; }
    else { j -= NWh4;              src = Wu; dh = g_Wuh; }
    float4 v = __ldg((const float4*)src + j);
    union { __half2 h[2]; uint2 q; } P;
    P.h[0] = __floats2half2_rn(v.x, v.y);
    P.h[1] = __floats2half2_rn(v.z, v.w);
    ((uint2*)dh)[j] = P.q;
}

__global__ __launch_bounds__(NTPRE) void k_pre(const int* __restrict__ rng,
                                               const float* __restrict__ Wz,
                                               const float* __restrict__ Wh,
                                               const float* __restrict__ Wu) {
    if (blockIdx.x == PREBLK) {
        __shared__ int sc[En], soff[En], scur[En];
        const int tid = threadIdx.x, lane = tid & 31;
        if (tid < En) { sc[tid] = 0; scur[tid] = 0; }
        __syncthreads();
        for (int i = tid; i < Bn; i += NTPRE) {
            int e = rng[i];
            unsigned m = __match_any_sync(0xffffffffu, e);
            if (lane == __ffs(m) - 1) atomicAdd(&sc[e], __popc(m));
        }
        __syncthreads();
        if (tid == 0) {
            int acc = 0, nt = 0;
            for (int e = 0; e < En; e++) {
                soff[e] = acc;
                int c = sc[e];
                for (int s = 0; s < c; s += TM) {
                    g_te[nt] = e;
                    g_ts[nt] = acc + s;
                    g_tr[nt] = (c - s) < TM ? (c - s) : TM;
                    nt++;
                }
                acc += c;
            }
            g_ntiles = nt;
        }
        __syncthreads();
        for (int i = tid; i < Bn; i += NTPRE) {
            int e = rng[i];
            unsigned m = __match_any_sync(0xffffffffu, e);
            int leader = __ffs(m) - 1;
            int rank = __popc(m & ((1u << lane) - 1u));
            int base = 0;
            if (lane == leader) base = atomicAdd(&scur[e], __popc(m));
            base = __shfl_sync(0xffffffffu, base, leader);
            g_perm[soff[e] + base + rank] = i;
        }
        return;
    }
    const int i0 = blockIdx.x * (NTPRE * 2) + threadIdx.x;
    cvt_one(i0, Wz, Wh, Wu);
    cvt_one(i0 + NTPRE, Wz, Wh, Wu);
}

// ---------------- A staging: gathered fp32 rows -> fp16 smem (all 512 thr) ----------------
__device__ __forceinline__ void stage_a32(char* smc, int off, const float* __restrict__ g,
                                          const int* ss, int tid) {
#pragma unroll
    for (int i = tid; i < TM * 32; i += NT) {
        int r = i >> 5, c = (i & 31) << 3;
        int s = ss[r];
        uint4 q = make_uint4(0u, 0u, 0u, 0u);
        if (s >= 0) {
            const float4 v0 = __ldg((const float4*)(g + (size_t)s * 256 + c));
            const float4 v1 = __ldg((const float4*)(g + (size_t)s * 256 + c + 4));
            union { __half2 h[4]; uint4 u; } P;
            P.h[0] = __floats2half2_rn(v0.x, v0.y);
            P.h[1] = __floats2half2_rn(v0.z, v0.w);
            P.h[2] = __floats2half2_rn(v1.x, v1.y);
            P.h[3] = __floats2half2_rn(v1.z, v1.w);
            q = P.u;
        }
        *(uint4*)(smc + off + (uint32_t)(r * LDA + c) * 2) = q;
    }
}

// B chunk: 128 rows x 64 halves via cp.async, staged by ONE group (256 threads)
__device__ __forceinline__ void stage_b(uint32_t bh, const __half* __restrict__ gh,
                                        int kc, int tidg) {
#pragma unroll
    for (int i = tidg; i < NCG * 8; i += 256) {
        int r = i >> 3, c = (i & 7) << 3;
        cpa16(bh + (uint32_t)(r * LDB + c) * 2, gh + (size_t)r * 256 + kc * KC + c);
    }
}

// ---------------- group GEMM: one 64x128 output chunk ----------------
// 8 warps (2x4), warp tile 32x32. Per-group 3-buffer ring (rot rotates across
// calls: 4 chunks == +1 mod 3). Group-scoped barrier only.
__device__ __forceinline__ void gemm_nc(uint32_t aB, uint32_t obsg, int rot, int gid,
                                        const __half* __restrict__ gB,
                                        float c[2][4][4], int tidg) {
    const int lane = tidg & 31, wig = tidg >> 5;
    const int wm = wig >> 2, wn = wig & 3;
    const int lrow = (lane & 7) + ((lane >> 3) & 1) * 8;
    const int lk8  = (lane >> 4) * 8;

#pragma unroll
    for (int mt = 0; mt < 2; mt++)
#pragma unroll
        for (int nt = 0; nt < 4; nt++)
#pragma unroll
            for (int j = 0; j < 4; j++) c[mt][nt][j] = 0.f;

    stage_b(obsg + (uint32_t)(rot % 3) * BPART, gB, 0, tidg);
    cpa_commit();

#pragma unroll
    for (int kc = 0; kc < 4; kc++) {
        if (kc < 3) {
            stage_b(obsg + (uint32_t)((rot + kc + 1) % 3) * BPART, gB, kc + 1, tidg);
            cpa_commit();
            cpa_wait<1>();
        } else {
            cpa_wait<0>();
        }
        gbar(1 + gid);

        const uint32_t bH = obsg + (uint32_t)((rot + kc) % 3) * BPART;
#pragma unroll
        for (int k16 = 0; k16 < 4; k16++) {
            const int ka = kc * KC + k16 * 16 + lk8;
            uint32_t ah[2][4];
#pragma unroll
            for (int mt = 0; mt < 2; mt++)
                ldm4(ah[mt], aB + (uint32_t)((wm * 32 + mt * 16 + lrow) * LDA + ka) * 2);
            uint32_t bf[2][4];
#pragma unroll
            for (int ng = 0; ng < 2; ng++)
                ldm4(bf[ng], bH + (uint32_t)((wn * 32 + ng * 16 + lrow) * LDB + k16 * 16 + lk8) * 2);
#pragma unroll
            for (int mt = 0; mt < 2; mt++)
#pragma unroll
                for (int nt = 0; nt < 4; nt++)
                    mma16816(c[mt][nt], ah[mt], bf[nt >> 1][nt & 1], bf[nt >> 1][(nt & 1) + 2]);
        }
    }
}

// ---------------- fused MoE kernel (2 independent 8-warp groups per CTA) ----------------
__global__ __launch_bounds__(NT, 1)
void k_moe(const float* __restrict__ z, const float* __restrict__ u,
           const float* __restrict__ bz, const float* __restrict__ bhb,
           float* __restrict__ out) {
    const int bt = blockIdx.x;
    if (bt >= g_ntiles) return;
    const int e = g_te[bt], start = g_ts[bt], rows = g_tr[bt];
    const int tid = threadIdx.x;
    const int gid = tid >> 8;            // group 0/1
    const int tidg = tid & 255;
    const int lane = tid & 31, wig = tidg >> 5;
    const int wm = wig >> 2, wn = wig & 3;
    const int t4 = lane >> 2, t2 = (lane & 3) * 2;

    extern __shared__ char smc[];
    const uint32_t sm0 = s2u(smc);
    const uint32_t aSH = sm0 + OASH, a2H = sm0 + OA2H;
    const uint32_t obsg = sm0 + OBS + (uint32_t)gid * 3 * BPART;

    __shared__ int ss[TM];
    if (tid < TM) ss[tid] = (tid < rows) ? g_perm[start + tid] : -1;
    __syncthreads();

    const __half* Wze = g_Wzh + (size_t)e * Zn * Zn;
    const __half* Whe = g_Whh + (size_t)e * Hn * Zn;
    const __half* Wue = g_Wuh + (size_t)e * Un * Un;

    stage_a32(smc, OASH, z, ss, tid);
    __syncthreads();                     // z tile fully staged

    float c[2][4][4];
    int rot = 0;                         // per-group ring rotation (+1 per call)

    // ---- GEMM1: a = z @ Wz^T + bz -> a2H (fp16); group covers N-half g*128 ----
    {
        const int n0 = gid * NCG;
        gemm_nc(aSH, obsg, rot, gid, Wze + (size_t)n0 * Zn, c, tidg); rot++;
        const float* bzp = bz + (size_t)e * Zn + n0;
#pragma unroll
        for (int mt = 0; mt < 2; mt++) {
            const int r0 = wm * 32 + mt * 16 + t4;
#pragma unroll
            for (int nt = 0; nt < 4; nt++) {
                const int col = wn * 32 + nt * 8 + t2;
                const float2 bb = *(const float2*)(bzp + col);
                uint32_t o = (uint32_t)(r0 * LDA + n0 + col) * 2;
                *(__half2*)(smc + OA2H + o) = __floats2half2_rn(c[mt][nt][0] + bb.x, c[mt][nt][1] + bb.y);
                o = (uint32_t)((r0 + 8) * LDA + n0 + col) * 2;
                *(__half2*)(smc + OA2H + o) = __floats2half2_rn(c[mt][nt][2] + bb.x, c[mt][nt][3] + bb.y);
            }
        }
    }
    __syncthreads();                     // a2H complete (both halves); aSH free

    stage_a32(smc, OASH, u, ss, tid);
    __syncthreads();                     // u tile fully staged; groups now drift freely

    // ---- GEMM2: h = relu(a @ Wh^T + bh) -> out; group N-half per 256-chunk ----
    {
        for (int nc = 0; nc < 4; nc++) {
            const int n0 = nc * 256 + gid * NCG;
            gemm_nc(a2H, obsg, rot, gid, Whe + (size_t)n0 * Zn, c, tidg); rot++;
            const float* bhp = bhb + (size_t)e * Hn + n0;
#pragma unroll
            for (int mt = 0; mt < 2; mt++) {
                const int r0 = wm * 32 + mt * 16 + t4;
                const int s0 = ss[r0], s1 = ss[r0 + 8];
#pragma unroll
                for (int nt = 0; nt < 4; nt++) {
                    const int col = wn * 32 + nt * 8 + t2;
                    const float2 bb = *(const float2*)(bhp + col);
                    if (s0 >= 0) {
                        float2 o;
                        o.x = fmaxf(c[mt][nt][0] + bb.x, 0.f);
                        o.y = fmaxf(c[mt][nt][1] + bb.y, 0.f);
                        *(float2*)(out + (size_t)s0 * Hn + n0 + col) = o;
                    }
                    if (s1 >= 0) {
                        float2 o;
                        o.x = fmaxf(c[mt][nt][2] + bb.x, 0.f);
                        o.y = fmaxf(c[mt][nt][3] + bb.y, 0.f);
                        *(float2*)(out + (size_t)s1 * Hn + n0 + col) = o;
                    }
                }
            }
        }
    }

    // ---- GEMM3: v = u @ Wu^T -> out + Bn*Hn; group N-half g*128 ----
    {
        const int n0 = gid * NCG;
        float* outv = out + (size_t)Bn * Hn;
        gemm_nc(aSH, obsg, rot, gid, Wue + (size_t)n0 * Zn, c, tidg); rot++;
#pragma unroll
        for (int mt = 0; mt < 2; mt++) {
            const int r0 = wm * 32 + mt * 16 + t4;
            const int s0 = ss[r0], s1 = ss[r0 + 8];
#pragma unroll
            for (int nt = 0; nt < 4; nt++) {
                const int col = wn * 32 + nt * 8 + t2;
                if (s0 >= 0) {
                    float2 o; o.x = c[mt][nt][0]; o.y = c[mt][nt][1];
                    *(float2*)(outv + (size_t)s0 * Un + n0 + col) = o;
                }
                if (s1 >= 0) {
                    float2 o; o.x = c[mt][nt][2]; o.y = c[mt][nt][3];
                    *(float2*)(outv + (size_t)s1 * Un + n0 + col) = o;
                }
            }
        }
    }
}

// ---------------- launcher ----------------
extern "C" void kernel_launch(void* const* d_in, const int* in_sizes, int n_in,
                              void* d_out, int out_size) {
    (void)in_sizes; (void)n_in; (void)out_size;
    const float* z   = (const float*)d_in[0];
    const float* u   = (const float*)d_in[1];
    const int*   rng = (const int*)d_in[2];
    const float* Wz  = (const float*)d_in[3];
    const float* bz  = (const float*)d_in[4];
    const float* Wh  = (const float*)d_in[5];
    const float* bh  = (const float*)d_in[6];
    const float* Wu  = (const float*)d_in[7];
    float* out = (float*)d_out;

    cudaFuncSetAttribute(k_moe, cudaFuncAttributeMaxDynamicSharedMemorySize, SMEM_DYN);

    k_pre<<<PREBLK + 1, NTPRE>>>(rng, Wz, Wh, Wu);
    k_moe<<<MAXT, NT, SMEM_DYN>>>(z, u, bz, bh, out);
}